// round 8
// baseline (speedup 1.0000x reference)
#include <cuda_runtime.h>
#include <cuda_bf16.h>

typedef unsigned long long ull;

// Transform-domain weights, duplicated pairs:
// g_wtd[ ((branch*9 + ds)*9 + tap)*16 + uv ] = (U, U)
// branch 0 = k, 1 = k'; ds = ds1*3+ds2; tap = dh1*3+dw1; uv = u*4+v
__device__ ull g_wtd[2592];
// Per-branch partial outputs (combined by combine_kernel)
__device__ float g_part[2][1048576];

__device__ __forceinline__ ull pack2(float x, float y) {
    ull r; asm("mov.b64 %0, {%1, %2};" : "=l"(r) : "f"(x), "f"(y)); return r;
}
__device__ __forceinline__ ull fma2(ull a, ull b, ull c) {
    ull d; asm("fma.rn.f32x2 %0, %1, %2, %3;" : "=l"(d) : "l"(a), "l"(b), "l"(c)); return d;
}
__device__ __forceinline__ float2 unpack2(ull v) {
    float2 f; asm("mov.b64 {%0, %1}, %2;" : "=f"(f.x), "=f"(f.y) : "l"(v)); return f;
}

__global__ void prep_kernel(const float* __restrict__ kern) {
    int i = threadIdx.x;
    if (i >= 162) return;
    int branch = i / 81;
    int r = i % 81;
    int ds = r / 9, tap = r % 9;
    int ds1 = ds / 3, ds2 = ds % 3;
    int dh1 = tap / 3, dw1 = tap % 3;
    float g[3][3];
    for (int a = 0; a < 3; a++)
        for (int b = 0; b < 3; b++) {
            int idx = (branch == 0)
                ? (((((ds1*3+ds2)*3+dh1)*3+dw1)*3+a)*3+b)
                : (((((ds2*3+ds1)*3+a)*3+b)*3+dh1)*3+dw1);
            g[a][b] = kern[idx];
        }
    // U = G g G^T,  G = [1,0,0; .5,.5,.5; .5,-.5,.5; 0,0,1]
    float t[4][3];
    for (int c = 0; c < 3; c++) {
        t[0][c] = g[0][c];
        t[1][c] = 0.5f*(g[0][c]+g[1][c]+g[2][c]);
        t[2][c] = 0.5f*(g[0][c]-g[1][c]+g[2][c]);
        t[3][c] = g[2][c];
    }
    int base = ((branch*9 + ds)*9 + tap)*16;
    for (int u = 0; u < 4; u++) {
        float U0 = t[u][0];
        float U1 = 0.5f*(t[u][0]+t[u][1]+t[u][2]);
        float U2 = 0.5f*(t[u][0]-t[u][1]+t[u][2]);
        float U3 = t[u][2];
        g_wtd[base + u*4 + 0] = pack2(U0, U0);
        g_wtd[base + u*4 + 1] = pack2(U1, U1);
        g_wtd[base + u*4 + 2] = pack2(U2, U2);
        g_wtd[base + u*4 + 3] = pack2(U3, U3);
    }
}

// ---------------------------------------------------------------------------
// Winograd F(2x2,3x3) over (h2,w2); one kernel-branch per CTA.
// Tile: (h1,w1,h2,w2) = (4,4,8,4). Grid = 2048 spatial tiles x 2 branches.
// 256 threads = q(16: h1*4+w1) x uv(16).
// SMEM floats:
//   [0,4608):   T  [plane 36][uv 16][ij 8]      (per-s_in, rebuilt 4x)
//   [4608,7488): raw [plane 36][h2h 10][w2h 8]  (6 valid + 2 pad)
//   [0,8192):   M  [q 16][so 4][ij 8][uv 16]    (epilogue overlay)
//   [8192,+2592): Wsm 1296 ull (this branch's (U,U) table)
// total 43136 B, 4 CTAs/SM, regs capped 64.
// ---------------------------------------------------------------------------
#define SMEM_BYTES 43136

__global__ __launch_bounds__(256, 4)
void conv_kernel(const float* __restrict__ x) {
    extern __shared__ float sm[];
    float* T   = sm;
    float* raw = sm + 4608;
    ull*   Wsm = (ull*)(sm + 8192);

    const int tid = threadIdx.x;
    const int bid = blockIdx.x;
    const int branch = bid & 1;
    const int bw2 = (bid >> 1) & 7;   // w2 tile (of 8, width 4)
    const int bh2 = (bid >> 4) & 3;   // h2 tile (of 4, width 8)
    const int bw1 = (bid >> 6) & 7;   // w1 tile (of 8, width 4)
    const int bh1 = bid >> 9;         // h1 tile (of 8, width 4)

    const int H1o = bh1 * 4 - 1, W1o = bw1 * 4 - 1;
    const int H2o = bh2 * 8 - 1, W2o = bw2 * 4 - 1;

    for (int i = tid; i < 1296; i += 256) Wsm[i] = g_wtd[branch * 1296 + i];

    const int q  = tid >> 4;
    const int uv = tid & 15;
    const int plane0 = (q >> 2) * 6 + (q & 3);   // h1*6 + w1

    ull acc[4][4];   // [ij-pair][so]
#pragma unroll
    for (int ip = 0; ip < 4; ip++)
#pragma unroll
        for (int so = 0; so < 4; so++) acc[ip][so] = 0ull;

#pragma unroll 1
    for (int s_in = 0; s_in < 4; s_in++) {
        __syncthreads();   // prior accumulate done before overwriting raw/T
        // ---- raw halo load: [36][10][8], relu'd, zero-padded ----
        for (int i = tid; i < 2880; i += 256) {
            int a4 = i & 7;
            int a3 = (i >> 3) % 10;
            int pl = i / 80;
            int a2 = pl % 6, a1 = pl / 6;
            int g1 = H1o + a1, g2 = W1o + a2, g3 = H2o + a3, g4 = W2o + a4;
            float v = 0.0f;
            if ((a4 < 6) && ((unsigned)g1 < 32u) && ((unsigned)g2 < 32u) &&
                ((unsigned)g3 < 32u) && ((unsigned)g4 < 32u)) {
                v = fmaxf(x[(((s_in * 32 + g1) * 32 + g2) * 32 + g3) * 32 + g4], 0.0f);
            }
            raw[i] = v;
        }
        __syncthreads();
        // ---- transform: 36 planes x 8 tiles, V = B^T d B ----
        for (int t = tid; t < 288; t += 256) {
            int plane = t >> 3;
            int ij = t & 7;
            int ti = ij >> 1, tj = ij & 1;
            const float* dp = raw + plane * 80 + (2*ti) * 8 + (2*tj);
            float d[4][4];
#pragma unroll
            for (int r = 0; r < 4; r++)
#pragma unroll
                for (int c = 0; c < 4; c++) d[r][c] = dp[r*8 + c];
            float tr[4][4];
#pragma unroll
            for (int c = 0; c < 4; c++) {
                tr[0][c] = d[0][c] - d[2][c];
                tr[1][c] = d[1][c] + d[2][c];
                tr[2][c] = d[2][c] - d[1][c];
                tr[3][c] = d[1][c] - d[3][c];
            }
            float* Tw = T + plane * 128 + ij;
#pragma unroll
            for (int u = 0; u < 4; u++) {
                float V0 = tr[u][0] - tr[u][2];
                float V1 = tr[u][1] + tr[u][2];
                float V2 = tr[u][2] - tr[u][1];
                float V3 = tr[u][1] - tr[u][3];
                Tw[(u*4 + 0) * 8] = V0;
                Tw[(u*4 + 1) * 8] = V1;
                Tw[(u*4 + 2) * 8] = V2;
                Tw[(u*4 + 3) * 8] = V3;
            }
        }
        __syncthreads();
        // ---- accumulate: 9 taps, ij-pairs straight from LDS.128 ----
        const int s1i = s_in >> 1, s2i = s_in & 1;
        const ull* wp0 = Wsm + (((s1i+1)*3 + (s2i+1)) * 144) + uv;  // so=0
        const ull* wp1 = Wsm + (((s1i+1)*3 +  s2i    ) * 144) + uv;  // so=1
        const ull* wp2 = Wsm + (( s1i   *3 + (s2i+1)) * 144) + uv;  // so=2
        const ull* wp3 = Wsm + (( s1i   *3 +  s2i    ) * 144) + uv;  // so=3
        const float* Tb = T + uv * 8;
#pragma unroll
        for (int dh1 = 0; dh1 < 3; dh1++) {
#pragma unroll
            for (int dw1 = 0; dw1 < 3; dw1++) {
                const float* Tp = Tb + (plane0 + dh1*6 + dw1) * 128;
                ulonglong2 tA = *(const ulonglong2*)Tp;        // ij 0-3
                ulonglong2 tB = *(const ulonglong2*)(Tp + 4);  // ij 4-7
                const int tw = (dh1*3 + dw1) * 16;
                ull w0 = wp0[tw], w1 = wp1[tw], w2 = wp2[tw], w3 = wp3[tw];
                acc[0][0] = fma2(tA.x, w0, acc[0][0]);
                acc[1][0] = fma2(tA.y, w0, acc[1][0]);
                acc[2][0] = fma2(tB.x, w0, acc[2][0]);
                acc[3][0] = fma2(tB.y, w0, acc[3][0]);
                acc[0][1] = fma2(tA.x, w1, acc[0][1]);
                acc[1][1] = fma2(tA.y, w1, acc[1][1]);
                acc[2][1] = fma2(tB.x, w1, acc[2][1]);
                acc[3][1] = fma2(tB.y, w1, acc[3][1]);
                acc[0][2] = fma2(tA.x, w2, acc[0][2]);
                acc[1][2] = fma2(tA.y, w2, acc[1][2]);
                acc[2][2] = fma2(tB.x, w2, acc[2][2]);
                acc[3][2] = fma2(tB.y, w2, acc[3][2]);
                acc[0][3] = fma2(tA.x, w3, acc[0][3]);
                acc[1][3] = fma2(tA.y, w3, acc[1][3]);
                acc[2][3] = fma2(tB.x, w3, acc[2][3]);
                acc[3][3] = fma2(tB.y, w3, acc[3][3]);
            }
        }
    }

    // ---- write M [q][so][ij][uv] ----
    __syncthreads();
    float* M = sm;
#pragma unroll
    for (int ip = 0; ip < 4; ip++)
#pragma unroll
        for (int so = 0; so < 4; so++) {
            float2 v = unpack2(acc[ip][so]);
            M[((q*4 + so)*8 + 2*ip    ) * 16 + uv] = v.x;
            M[((q*4 + so)*8 + 2*ip + 1) * 16 + uv] = v.y;
        }
    __syncthreads();

    // ---- inverse transform + sigmoid + mask; each thread: 2 of 4 so ----
    {
        const int a   = tid >> 7;          // so-half
        const int rem = tid & 127;
        const int q2  = rem >> 3;
        const int ij  = rem & 7;
        const int ti = ij >> 1, tj = ij & 1;
        const int H1 = bh1*4 + (q2 >> 2), W1 = bw1*4 + (q2 & 3);
        const int H2 = bh2*8 + 2*ti,      W2 = bw2*4 + 2*tj;

        float part[4] = {0.f, 0.f, 0.f, 0.f};
#pragma unroll
        for (int s = 0; s < 2; s++) {
            int so = 2*a + s;
            const float* mp = M + ((q2*4 + so)*8 + ij) * 16;
            float m[16];
#pragma unroll
            for (int u = 0; u < 16; u += 4) {
                float4 mv = *(const float4*)(mp + u);
                m[u] = mv.x; m[u+1] = mv.y; m[u+2] = mv.z; m[u+3] = mv.w;
            }
            float p0[4], p1[4];
#pragma unroll
            for (int c = 0; c < 4; c++) {
                p0[c] = m[c] + m[4+c] + m[8+c];
                p1[c] = m[4+c] - m[8+c] - m[12+c];
            }
            float y00 = p0[0] + p0[1] + p0[2];
            float y01 = p0[1] - p0[2] - p0[3];
            float y10 = p1[0] + p1[1] + p1[2];
            float y11 = p1[1] - p1[2] - p1[3];
            const float* xs = x + so * 1048576 + ((H1*32 + W1)*32 + H2)*32 + W2;
            float2 x0 = *(const float2*)xs;
            float2 x1 = *(const float2*)(xs + 32);
            part[0] += (x0.x != 0.0f) ? 1.0f/(1.0f+__expf(-y00)) : 0.0f;
            part[1] += (x0.y != 0.0f) ? 1.0f/(1.0f+__expf(-y01)) : 0.0f;
            part[2] += (x1.x != 0.0f) ? 1.0f/(1.0f+__expf(-y10)) : 0.0f;
            part[3] += (x1.y != 0.0f) ? 1.0f/(1.0f+__expf(-y11)) : 0.0f;
        }
        __syncthreads();
        float* scr = (float*)Wsm;    // W no longer needed
        if (a == 1)
            *(float4*)(scr + rem*4) = make_float4(part[0], part[1], part[2], part[3]);
        __syncthreads();
        if (a == 0) {
            float4 o = *(const float4*)(scr + rem*4);
            part[0] += o.x; part[1] += o.y; part[2] += o.z; part[3] += o.w;
            float* gp = g_part[branch] + ((H1*32 + W1)*32 + H2)*32 + W2;
            *(float2*)gp        = make_float2(part[0], part[1]);
            *(float2*)(gp + 32) = make_float2(part[2], part[3]);
        }
    }
}

__global__ void combine_kernel(float* __restrict__ out) {
    int i = (blockIdx.x * 256 + threadIdx.x) * 4;
    float4 a = *(const float4*)(g_part[0] + i);
    float4 b = *(const float4*)(g_part[1] + i);
    *(float4*)(out + i) = make_float4(a.x + b.x, a.y + b.y, a.z + b.z, a.w + b.w);
}

extern "C" void kernel_launch(void* const* d_in, const int* in_sizes, int n_in,
                              void* d_out, int out_size) {
    const float* x    = (const float*)d_in[0];   // (1,2,2,32,32,32,32)
    const float* kern = (const float*)d_in[1];   // (729,)
    float* out = (float*)d_out;                  // (1,32,32,32,32)

    prep_kernel<<<1, 192>>>(kern);

    cudaFuncSetAttribute(conv_kernel,
                         cudaFuncAttributeMaxDynamicSharedMemorySize, SMEM_BYTES);
    conv_kernel<<<4096, 256, SMEM_BYTES>>>(x);

    combine_kernel<<<1024, 256>>>(out);
}

// round 9
// speedup vs baseline: 1.4360x; 1.4360x over previous
#include <cuda_runtime.h>
#include <cuda_bf16.h>

typedef unsigned long long ull;

// Transform-domain weights, duplicated pairs:
// g_wtd[ ((br*9 + ds)*9 + tap)*16 + uv ] = (U, U)
// br 0 = k, 1 = k'; ds = ds1*3+ds2; tap = dh1*3+dw1; uv = u*4+v
__device__ ull g_wtd[2592];

__device__ __forceinline__ ull pack2(float x, float y) {
    ull r; asm("mov.b64 %0, {%1, %2};" : "=l"(r) : "f"(x), "f"(y)); return r;
}
__device__ __forceinline__ ull fma2(ull a, ull b, ull c) {
    ull d; asm("fma.rn.f32x2 %0, %1, %2, %3;" : "=l"(d) : "l"(a), "l"(b), "l"(c)); return d;
}
__device__ __forceinline__ float2 unpack2(ull v) {
    float2 f; asm("mov.b64 {%0, %1}, %2;" : "=f"(f.x), "=f"(f.y) : "l"(v)); return f;
}
__device__ __forceinline__ float sigm(float v) {
    return 1.0f / (1.0f + __expf(-v));
}

__global__ void prep_kernel(const float* __restrict__ kern) {
    int i = threadIdx.x;
    if (i >= 162) return;
    int branch = i / 81;
    int r = i % 81;
    int ds = r / 9, tap = r % 9;
    int ds1 = ds / 3, ds2 = ds % 3;
    int dh1 = tap / 3, dw1 = tap % 3;
    float g[3][3];
    for (int a = 0; a < 3; a++)
        for (int b = 0; b < 3; b++) {
            int idx = (branch == 0)
                ? (((((ds1*3+ds2)*3+dh1)*3+dw1)*3+a)*3+b)
                : (((((ds2*3+ds1)*3+a)*3+b)*3+dh1)*3+dw1);
            g[a][b] = kern[idx];
        }
    float t[4][3];
    for (int c = 0; c < 3; c++) {
        t[0][c] = g[0][c];
        t[1][c] = 0.5f*(g[0][c]+g[1][c]+g[2][c]);
        t[2][c] = 0.5f*(g[0][c]-g[1][c]+g[2][c]);
        t[3][c] = g[2][c];
    }
    int base = ((branch*9 + ds)*9 + tap)*16;
    for (int u = 0; u < 4; u++) {
        float U0 = t[u][0];
        float U1 = 0.5f*(t[u][0]+t[u][1]+t[u][2]);
        float U2 = 0.5f*(t[u][0]-t[u][1]+t[u][2]);
        float U3 = t[u][2];
        g_wtd[base + u*4 + 0] = pack2(U0, U0);
        g_wtd[base + u*4 + 1] = pack2(U1, U1);
        g_wtd[base + u*4 + 2] = pack2(U2, U2);
        g_wtd[base + u*4 + 3] = pack2(U3, U3);
    }
}

// ---------------------------------------------------------------------------
// Winograd F(2x2,3x3) over (h2,w2), both branches in one CTA.
// Tile: (h1,w1,h2,w2) = (2,4,8,8). Grid = 16*8*4*4 = 2048 CTAs.
// 512 threads = q(8 = h1(2) x w1(4)) x so(4) x uv(16).
// Per-thread acc: 16 ij as 8 ull pairs x 2 branches = 16 ull (32 regs).
// SMEM floats:
//   phase A: T [24 planes][uv16 * 20] stride 336/plane  (8064 fl)
//            raw [24][10][12] at offset 8064            (2880 fl)
//   phase B: M [64 regions][ij16 * 20] stride 328       (20992 fl, overlays A)
//   W: 2592 ull at float-offset 20992                   (20736 B)
//   scr: 2048 fl (epilogue, overlays W)
// total = 20992*4 + 20736 = 104704 B -> 2 CTAs/SM.
// ---------------------------------------------------------------------------
#define SMEM_BYTES 104704

__global__ __launch_bounds__(512, 2)
void conv_kernel(const float* __restrict__ x, float* __restrict__ out) {
    extern __shared__ float sm[];
    float* T   = sm;
    float* raw = sm + 8064;
    float* M   = sm;                       // overlay after accumulate
    ull*   Wsm = (ull*)(sm + 20992);
    float* scr = sm + 20992;               // overlay after accumulate

    const int tid = threadIdx.x;
    const int bid = blockIdx.x;
    const int bw2 = bid & 3;
    const int bh2 = (bid >> 2) & 3;
    const int bw1 = (bid >> 4) & 7;
    const int bh1 = bid >> 7;              // 0..15

    const int H1o = bh1 * 2 - 1, W1o = bw1 * 4 - 1;
    const int H2o = bh2 * 8 - 1, W2o = bw2 * 8 - 1;

    for (int i = tid; i < 2592; i += 512) Wsm[i] = g_wtd[i];

    const int uv = tid & 15;
    const int so = (tid >> 4) & 3;
    const int q  = tid >> 6;               // 0..7
    const int h1q = q >> 2, w1q = q & 3;
    const int plane0 = h1q * 6 + w1q;
    const int s1o = so >> 1, s2o = so & 1;

    ull accK[8], accT[8];
#pragma unroll
    for (int i = 0; i < 8; i++) { accK[i] = 0ull; accT[i] = 0ull; }

#pragma unroll 1
    for (int s_in = 0; s_in < 4; s_in++) {
        __syncthreads();
        // ---- raw halo load [24][10][12], relu'd, zero-padded ----
        for (int i = tid; i < 2880; i += 512) {
            int a4 = i % 12;
            int a3 = (i / 12) % 10;
            int pl = i / 120;
            int a1 = pl / 6, a2 = pl % 6;
            int g1 = H1o + a1, g2 = W1o + a2, g3 = H2o + a3, g4 = W2o + a4;
            float v = 0.0f;
            if ((a4 < 10) && ((unsigned)g1 < 32u) && ((unsigned)g2 < 32u) &&
                ((unsigned)g3 < 32u) && ((unsigned)g4 < 32u)) {
                v = fmaxf(x[(((s_in * 32 + g1) * 32 + g2) * 32 + g3) * 32 + g4], 0.0f);
            }
            raw[i] = v;
        }
        __syncthreads();
        // ---- input transform: 24 planes x 16 tiles ----
        if (tid < 384) {
            int plane = tid >> 4;
            int ij = tid & 15;
            int ti = ij >> 2, tj = ij & 3;
            const float* dp = raw + plane * 120 + (2*ti) * 12 + 2*tj;
            float d[4][4];
#pragma unroll
            for (int r = 0; r < 4; r++)
#pragma unroll
                for (int c = 0; c < 4; c++) d[r][c] = dp[r*12 + c];
            float tr[4][4];
#pragma unroll
            for (int c = 0; c < 4; c++) {
                tr[0][c] = d[0][c] - d[2][c];
                tr[1][c] = d[1][c] + d[2][c];
                tr[2][c] = d[2][c] - d[1][c];
                tr[3][c] = d[1][c] - d[3][c];
            }
            float* Tw = T + plane * 336 + ij;
#pragma unroll
            for (int u = 0; u < 4; u++) {
                float V0 = tr[u][0] - tr[u][2];
                float V1 = tr[u][1] + tr[u][2];
                float V2 = tr[u][2] - tr[u][1];
                float V3 = tr[u][1] - tr[u][3];
                Tw[(u*4 + 0) * 20] = V0;
                Tw[(u*4 + 1) * 20] = V1;
                Tw[(u*4 + 2) * 20] = V2;
                Tw[(u*4 + 3) * 20] = V3;
            }
        }
        __syncthreads();
        // ---- transform-domain accumulate: 9 taps ----
        const int s1i = s_in >> 1, s2i = s_in & 1;
        const int ds = (s1i - s1o + 1) * 3 + (s2i - s2o + 1);
        const ull* Wb = Wsm + ds * 144 + uv;
        const float* Tb = T + plane0 * 336 + uv * 20;
#pragma unroll
        for (int dh1 = 0; dh1 < 3; dh1++) {
#pragma unroll
            for (int dw1 = 0; dw1 < 3; dw1++) {
                const float* Tp = Tb + (dh1*6 + dw1) * 336;
                ulonglong2 t0 = *(const ulonglong2*)(Tp);
                ulonglong2 t1 = *(const ulonglong2*)(Tp + 4);
                ulonglong2 t2 = *(const ulonglong2*)(Tp + 8);
                ulonglong2 t3 = *(const ulonglong2*)(Tp + 12);
                const int tw = (dh1*3 + dw1) * 16;
                ull wk = Wb[tw];
                ull wt = Wb[1296 + tw];
                accK[0] = fma2(t0.x, wk, accK[0]);
                accK[1] = fma2(t0.y, wk, accK[1]);
                accK[2] = fma2(t1.x, wk, accK[2]);
                accK[3] = fma2(t1.y, wk, accK[3]);
                accK[4] = fma2(t2.x, wk, accK[4]);
                accK[5] = fma2(t2.y, wk, accK[5]);
                accK[6] = fma2(t3.x, wk, accK[6]);
                accK[7] = fma2(t3.y, wk, accK[7]);
                accT[0] = fma2(t0.x, wt, accT[0]);
                accT[1] = fma2(t0.y, wt, accT[1]);
                accT[2] = fma2(t1.x, wt, accT[2]);
                accT[3] = fma2(t1.y, wt, accT[3]);
                accT[4] = fma2(t2.x, wt, accT[4]);
                accT[5] = fma2(t2.y, wt, accT[5]);
                accT[6] = fma2(t3.x, wt, accT[6]);
                accT[7] = fma2(t3.y, wt, accT[7]);
            }
        }
    }

    // ---- write M: region (q*4+so)*2+br, [ij][uv] with ij stride 20 ----
    __syncthreads();
    {
        float* M0 = M + ((q*4 + so)*2) * 328 + uv;
#pragma unroll
        for (int ip = 0; ip < 8; ip++) {
            float2 vk = unpack2(accK[ip]);
            float2 vt = unpack2(accT[ip]);
            M0[(2*ip    )*20]       = vk.x;
            M0[(2*ip + 1)*20]       = vk.y;
            M0[328 + (2*ip    )*20] = vt.x;
            M0[328 + (2*ip + 1)*20] = vt.y;
        }
    }
    __syncthreads();

    // ---- epilogue 1: inverse transform both branches, sigmoid, mask ----
    {
        const int ij = uv;
        const int ti = ij >> 2, tj = ij & 3;
        const int H1 = bh1*2 + h1q, W1 = bw1*4 + w1q;
        const int H2 = bh2*8 + 2*ti, W2 = bw2*8 + 2*tj;

        float p00 = 0.f, p01 = 0.f, p10 = 0.f, p11 = 0.f;
        const float* Mr = M + ((q*4 + so)*2) * 328 + ij * 20;
#pragma unroll
        for (int br = 0; br < 2; br++) {
            float m[16];
#pragma unroll
            for (int u = 0; u < 16; u += 4) {
                float4 mv = *(const float4*)(Mr + br*328 + u);
                m[u] = mv.x; m[u+1] = mv.y; m[u+2] = mv.z; m[u+3] = mv.w;
            }
            float p0[4], p1[4];
#pragma unroll
            for (int c = 0; c < 4; c++) {
                p0[c] = m[c] + m[4+c] + m[8+c];
                p1[c] = m[4+c] - m[8+c] - m[12+c];
            }
            p00 += sigm(p0[0] + p0[1] + p0[2]);
            p01 += sigm(p0[1] - p0[2] - p0[3]);
            p10 += sigm(p1[0] + p1[1] + p1[2]);
            p11 += sigm(p1[1] - p1[2] - p1[3]);
        }
        const float* xs = x + so * 1048576 + ((H1*32 + W1)*32 + H2)*32 + W2;
        float2 x0 = *(const float2*)xs;
        float2 x1 = *(const float2*)(xs + 32);
        float v0 = (x0.x != 0.0f) ? p00 : 0.0f;
        float v1 = (x0.y != 0.0f) ? p01 : 0.0f;
        float v2 = (x1.x != 0.0f) ? p10 : 0.0f;
        float v3 = (x1.y != 0.0f) ? p11 : 0.0f;
        *(float4*)(scr + ((q*16 + ij)*4 + so)*4) = make_float4(v0, v1, v2, v3);
    }
    __syncthreads();

    // ---- epilogue 2: sum over so, store ----
    if (tid < 128) {
        int q2 = tid >> 4, ij = tid & 15;
        const float* s4 = scr + (q2*16 + ij)*16;
        float4 a = *(const float4*)(s4);
        float4 b = *(const float4*)(s4 + 4);
        float4 c = *(const float4*)(s4 + 8);
        float4 d = *(const float4*)(s4 + 12);
        float o0 = a.x + b.x + c.x + d.x;
        float o1 = a.y + b.y + c.y + d.y;
        float o2 = a.z + b.z + c.z + d.z;
        float o3 = a.w + b.w + c.w + d.w;
        int ti = ij >> 2, tj = ij & 3;
        int H1 = bh1*2 + (q2 >> 2), W1 = bw1*4 + (q2 & 3);
        int H2 = bh2*8 + 2*ti,      W2 = bw2*8 + 2*tj;
        float* op = out + ((H1*32 + W1)*32 + H2)*32 + W2;
        *(float2*)op        = make_float2(o0, o1);
        *(float2*)(op + 32) = make_float2(o2, o3);
    }
}

extern "C" void kernel_launch(void* const* d_in, const int* in_sizes, int n_in,
                              void* d_out, int out_size) {
    const float* x    = (const float*)d_in[0];   // (1,2,2,32,32,32,32)
    const float* kern = (const float*)d_in[1];   // (729,)
    float* out = (float*)d_out;                  // (1,32,32,32,32)

    prep_kernel<<<1, 192>>>(kern);

    cudaFuncSetAttribute(conv_kernel,
                         cudaFuncAttributeMaxDynamicSharedMemorySize, SMEM_BYTES);
    conv_kernel<<<2048, 512, SMEM_BYTES>>>(x, out);
}

// round 11
// speedup vs baseline: 1.8864x; 1.3137x over previous
#include <cuda_runtime.h>
#include <cuda_bf16.h>

typedef unsigned long long ull;

// Global transform-domain input: [s 4][g1 32][g2 32][tile 256][uv 16] floats
__device__ float g_T[16777216];
// Weight pairs over uv: g_wp2[((ds*9+tap)*8 + uvp)*2 + br] = (U[2uvp], U[2uvp+1])
__device__ ull g_wp2[1296];

__device__ __forceinline__ ull pack2(float x, float y) {
    ull r; asm("mov.b64 %0, {%1, %2};" : "=l"(r) : "f"(x), "f"(y)); return r;
}
__device__ __forceinline__ ull fma2(ull a, ull b, ull c) {
    ull d; asm("fma.rn.f32x2 %0, %1, %2, %3;" : "=l"(d) : "l"(a), "l"(b), "l"(c)); return d;
}
__device__ __forceinline__ float sigm(float v) { return 1.0f / (1.0f + __expf(-v)); }

// ---------------------------------------------------------------------------
// Weight prep: U = G g G^T per (branch, ds, tap), stored as uv-adjacent pairs.
// ---------------------------------------------------------------------------
__global__ void prep_kernel(const float* __restrict__ kern) {
    int i = threadIdx.x;
    if (i >= 162) return;
    int br = i / 81;
    int r  = i % 81;
    int ds = r / 9, tap = r % 9;
    int ds1 = ds / 3, ds2 = ds % 3;
    int dh1 = tap / 3, dw1 = tap % 3;
    float g[3][3];
    for (int a = 0; a < 3; a++)
        for (int b = 0; b < 3; b++) {
            int idx = (br == 0)
                ? (((((ds1*3+ds2)*3+dh1)*3+dw1)*3+a)*3+b)
                : (((((ds2*3+ds1)*3+a)*3+b)*3+dh1)*3+dw1);
            g[a][b] = kern[idx];
        }
    float t[4][3];
    for (int c = 0; c < 3; c++) {
        t[0][c] = g[0][c];
        t[1][c] = 0.5f*(g[0][c]+g[1][c]+g[2][c]);
        t[2][c] = 0.5f*(g[0][c]-g[1][c]+g[2][c]);
        t[3][c] = g[2][c];
    }
    for (int u = 0; u < 4; u++) {
        float U[4];
        U[0] = t[u][0];
        U[1] = 0.5f*(t[u][0]+t[u][1]+t[u][2]);
        U[2] = 0.5f*(t[u][0]-t[u][1]+t[u][2]);
        U[3] = t[u][2];
        for (int vp = 0; vp < 2; vp++) {
            int uvp = u*2 + vp;
            g_wp2[((ds*9+tap)*8 + uvp)*2 + br] = pack2(U[2*vp], U[2*vp+1]);
        }
    }
}

// ---------------------------------------------------------------------------
// Kernel 1: global input transform. One thread per (s, g1, g2, 4x4 patch).
// V = B^T d B with relu'd, zero-padded x; patch origin (2*ti-1, 2*tj-1).
// ---------------------------------------------------------------------------
__global__ __launch_bounds__(256)
void xform_kernel(const float* __restrict__ x) {
    int gid = blockIdx.x * 256 + threadIdx.x;     // 0 .. 1048575
    int tt = gid & 255;
    int ti = tt >> 4, tj = tt & 15;
    int pg = gid >> 8;                            // s*1024 + g1*32 + g2
    const float* xs = x + pg * 1024;
    int h0 = 2*ti - 1, w0 = 2*tj - 1;
    float d[4][4];
#pragma unroll
    for (int r = 0; r < 4; r++) {
#pragma unroll
        for (int c = 0; c < 4; c++) {
            int h = h0 + r, w = w0 + c;
            float v = 0.0f;
            if (((unsigned)h < 32u) && ((unsigned)w < 32u))
                v = fmaxf(xs[h*32 + w], 0.0f);
            d[r][c] = v;
        }
    }
    float tr[4][4];
#pragma unroll
    for (int c = 0; c < 4; c++) {
        tr[0][c] = d[0][c] - d[2][c];
        tr[1][c] = d[1][c] + d[2][c];
        tr[2][c] = d[2][c] - d[1][c];
        tr[3][c] = d[1][c] - d[3][c];
    }
    float* o = g_T + gid * 16;
#pragma unroll
    for (int u = 0; u < 4; u++) {
        float V0 = tr[u][0] - tr[u][2];
        float V1 = tr[u][1] + tr[u][2];
        float V2 = tr[u][2] - tr[u][1];
        float V3 = tr[u][1] - tr[u][3];
        *(float4*)(o + u*4) = make_float4(V0, V1, V2, V3);
    }
}

// ---------------------------------------------------------------------------
// Kernel 2: transform-domain accumulate + inverse + sigmoid/mask/sum.
// CTA: (h1,w1) 4x4 region x 4x4 tile-block (8x8 h2w2) = 1024 outputs.
// 128 threads = tile-local tl(16) x uvp(8). 8 phases of (h1, w1-half).
// acc[wl 2][so 4][br 2] ull (uv-pair packed) = 16 ull.
// SMEM: Wsm 1296 ull (10368 B) + M [2][16][136] fl (17408 B) = 27776 B.
// ---------------------------------------------------------------------------
#define SMEM_BYTES 27776

__global__ __launch_bounds__(128, 6)
void conv_kernel(const float* __restrict__ x, float* __restrict__ out) {
    extern __shared__ float sm[];
    ull* Wsm = (ull*)sm;
    float* M = sm + 2592;

    const int tid = threadIdx.x;
    const int bid = blockIdx.x;
    const int B2  = bid & 3;
    const int B1  = (bid >> 2) & 3;
    const int bw1 = (bid >> 4) & 7;
    const int bh1 = bid >> 7;

    for (int i = tid; i < 1296; i += 128) Wsm[i] = g_wp2[i];

    const int uvp = tid & 7;
    const int tl  = tid >> 3;
    const int ta  = tl >> 2, tb = tl & 3;
    const long toff = (((B1*4 + ta)*16 + (B2*4 + tb))*16) + 2*uvp;
    const ulonglong2* Wq = (const ulonglong2*)Wsm;
    __syncthreads();

#pragma unroll 1
    for (int qb = 0; qb < 8; qb++) {
        const int h1  = qb >> 1;
        const int w1h = qb & 1;
        const int H1  = bh1*4 + h1;
        const int g2c = bw1*4 + w1h*2 - 1;

        ull acc[2][4][2];
#pragma unroll
        for (int wl = 0; wl < 2; wl++)
#pragma unroll
            for (int so = 0; so < 4; so++) { acc[wl][so][0] = 0ull; acc[wl][so][1] = 0ull; }

#pragma unroll 1
        for (int s_in = 0; s_in < 4; s_in++) {
            const int s1i = s_in >> 1, s2i = s_in & 1;
            const int b0 = ((s1i+1)*3 + s2i+1) * 72 + uvp;   // so=0
            const int b1 = ((s1i+1)*3 + s2i  ) * 72 + uvp;   // so=1
            const int b2 = ( s1i   *3 + s2i+1) * 72 + uvp;   // so=2
            const int b3 = ( s1i   *3 + s2i  ) * 72 + uvp;   // so=3
            const float* Ts = g_T + (long)s_in * 4194304 + toff;
#pragma unroll
            for (int dh1 = 0; dh1 < 3; dh1++) {
                int g1 = H1 + dh1 - 1;
                if ((unsigned)g1 >= 32u) continue;
                const float* Tg2 = Ts + (long)g1 * 131072 + (long)g2c * 4096;
#pragma unroll
                for (int dw1 = 0; dw1 < 3; dw1++) {
                    const int tap8 = (dh1*3 + dw1) * 8;
                    ulonglong2 w0 = Wq[b0 + tap8];
                    ulonglong2 w1 = Wq[b1 + tap8];
                    ulonglong2 w2 = Wq[b2 + tap8];
                    ulonglong2 w3 = Wq[b3 + tap8];
                    const float* Tp = Tg2 + dw1 * 4096;
#pragma unroll
                    for (int wl = 0; wl < 2; wl++) {
                        int g2 = g2c + dw1 + wl;
                        ull tv = 0ull;
                        if ((unsigned)g2 < 32u) tv = *(const ull*)(Tp + wl*4096);
                        acc[wl][0][0] = fma2(tv, w0.x, acc[wl][0][0]);
                        acc[wl][0][1] = fma2(tv, w0.y, acc[wl][0][1]);
                        acc[wl][1][0] = fma2(tv, w1.x, acc[wl][1][0]);
                        acc[wl][1][1] = fma2(tv, w1.y, acc[wl][1][1]);
                        acc[wl][2][0] = fma2(tv, w2.x, acc[wl][2][0]);
                        acc[wl][2][1] = fma2(tv, w2.y, acc[wl][2][1]);
                        acc[wl][3][0] = fma2(tv, w3.x, acc[wl][3][0]);
                        acc[wl][3][1] = fma2(tv, w3.y, acc[wl][3][1]);
                    }
                }
            }
        }

        __syncthreads();   // prior epilogue done; safe to overwrite M
#pragma unroll
        for (int wl = 0; wl < 2; wl++)
#pragma unroll
            for (int so = 0; so < 4; so++)
#pragma unroll
                for (int br = 0; br < 2; br++)
                    *(ull*)(M + (wl*16 + tl)*136 + (so*2 + br)*16 + 2*uvp)
                        = acc[wl][so][br];
        __syncthreads();

        // ---- inverse + sigmoid + mask + so-reduction; item = tid ----
        {
            const int so = tid & 3;
            const int t  = (tid >> 2) & 15;
            const int wl = tid >> 6;
            const int w1 = w1h*2 + wl;
            const int W1 = bw1*4 + w1;
            const int ti = B1*4 + (t >> 2);
            const int tj = B2*4 + (t & 3);
            const float* mc = M + (wl*16 + t)*136 + so*32;

            float p[4] = {0.f, 0.f, 0.f, 0.f};
#pragma unroll
            for (int br = 0; br < 2; br++) {
                float m[16];
#pragma unroll
                for (int u = 0; u < 16; u += 4) {
                    float4 mv = *(const float4*)(mc + br*16 + u);
                    m[u] = mv.x; m[u+1] = mv.y; m[u+2] = mv.z; m[u+3] = mv.w;
                }
                float p0[4], p1[4];
#pragma unroll
                for (int c = 0; c < 4; c++) {
                    p0[c] = m[c] + m[4+c] + m[8+c];
                    p1[c] = m[4+c] - m[8+c] - m[12+c];
                }
                p[0] += sigm(p0[0] + p0[1] + p0[2]);
                p[1] += sigm(p0[1] - p0[2] - p0[3]);
                p[2] += sigm(p1[0] + p1[1] + p1[2]);
                p[3] += sigm(p1[1] - p1[2] - p1[3]);
            }
            const float* xs = x + so*1048576 + (H1*32 + W1)*1024 + (2*ti)*32 + 2*tj;
            float2 x0 = *(const float2*)xs;
            float2 x1 = *(const float2*)(xs + 32);
            p[0] = (x0.x != 0.0f) ? p[0] : 0.0f;
            p[1] = (x0.y != 0.0f) ? p[1] : 0.0f;
            p[2] = (x1.x != 0.0f) ? p[2] : 0.0f;
            p[3] = (x1.y != 0.0f) ? p[3] : 0.0f;
#pragma unroll
            for (int k = 0; k < 4; k++) {
                p[k] += __shfl_xor_sync(0xFFFFFFFFu, p[k], 1);
                p[k] += __shfl_xor_sync(0xFFFFFFFFu, p[k], 2);
            }
            if (so == 0) {
                float* op = out + (H1*32 + W1)*1024 + (2*ti)*32 + 2*tj;
                *(float2*)op        = make_float2(p[0], p[1]);
                *(float2*)(op + 32) = make_float2(p[2], p[3]);
            }
        }
        // next iteration's first __syncthreads() orders this epilogue
        // before the next M overwrite.
    }
}

extern "C" void kernel_launch(void* const* d_in, const int* in_sizes, int n_in,
                              void* d_out, int out_size) {
    const float* x    = (const float*)d_in[0];   // (1,2,2,32,32,32,32)
    const float* kern = (const float*)d_in[1];   // (729,)
    float* out = (float*)d_out;                  // (1,32,32,32,32)

    prep_kernel<<<1, 192>>>(kern);
    xform_kernel<<<4096, 256>>>(x);
    conv_kernel<<<1024, 128, SMEM_BYTES>>>(x, out);
}

// round 12
// speedup vs baseline: 2.2235x; 1.1787x over previous
#include <cuda_runtime.h>
#include <cuda_bf16.h>

typedef unsigned long long ull;

// Zero-padded transform-domain input: [s 4][g1p 34][g2p 34][tile 256][uv 16]
// Borders (g1p=0,33 / g2p=0,33) are never written -> stay zero (static init).
__device__ float g_T[18939904];
// Weight pairs over uv: g_wp2[((ds*9+tap)*8 + uvp)*2 + br] = (U[2uvp], U[2uvp+1])
__device__ ull g_wp2[1296];

__device__ __forceinline__ ull pack2(float x, float y) {
    ull r; asm("mov.b64 %0, {%1, %2};" : "=l"(r) : "f"(x), "f"(y)); return r;
}
__device__ __forceinline__ ull fma2(ull a, ull b, ull c) {
    ull d; asm("fma.rn.f32x2 %0, %1, %2, %3;" : "=l"(d) : "l"(a), "l"(b), "l"(c)); return d;
}
__device__ __forceinline__ float sigm(float v) { return 1.0f / (1.0f + __expf(-v)); }

// ---------------------------------------------------------------------------
// Kernel 1: global input transform (+ weight prep in the extra block).
// ---------------------------------------------------------------------------
__global__ __launch_bounds__(256)
void xform_kernel(const float* __restrict__ x, const float* __restrict__ kern) {
    if (blockIdx.x == 4096) {
        // ---- weight prep: U = G g G^T per (branch, ds, tap) ----
        int i = threadIdx.x;
        if (i >= 162) return;
        int br = i / 81;
        int r  = i % 81;
        int ds = r / 9, tap = r % 9;
        int ds1 = ds / 3, ds2 = ds % 3;
        int dh1 = tap / 3, dw1 = tap % 3;
        float g[3][3];
        for (int a = 0; a < 3; a++)
            for (int b = 0; b < 3; b++) {
                int idx = (br == 0)
                    ? (((((ds1*3+ds2)*3+dh1)*3+dw1)*3+a)*3+b)
                    : (((((ds2*3+ds1)*3+a)*3+b)*3+dh1)*3+dw1);
                g[a][b] = kern[idx];
            }
        float t[4][3];
        for (int c = 0; c < 3; c++) {
            t[0][c] = g[0][c];
            t[1][c] = 0.5f*(g[0][c]+g[1][c]+g[2][c]);
            t[2][c] = 0.5f*(g[0][c]-g[1][c]+g[2][c]);
            t[3][c] = g[2][c];
        }
        for (int u = 0; u < 4; u++) {
            float U[4];
            U[0] = t[u][0];
            U[1] = 0.5f*(t[u][0]+t[u][1]+t[u][2]);
            U[2] = 0.5f*(t[u][0]-t[u][1]+t[u][2]);
            U[3] = t[u][2];
            for (int vp = 0; vp < 2; vp++) {
                int uvp = u*2 + vp;
                g_wp2[((ds*9+tap)*8 + uvp)*2 + br] = pack2(U[2*vp], U[2*vp+1]);
            }
        }
        return;
    }
    int gid = blockIdx.x * 256 + threadIdx.x;     // 0 .. 1048575
    int tt = gid & 255;
    int ti = tt >> 4, tj = tt & 15;
    int pg = gid >> 8;                            // s*1024 + g1*32 + g2
    int g2 = pg & 31, g1 = (pg >> 5) & 31, s = pg >> 10;
    const float* xs = x + pg * 1024;
    int h0 = 2*ti - 1, w0 = 2*tj - 1;
    float d[4][4];
#pragma unroll
    for (int r = 0; r < 4; r++) {
#pragma unroll
        for (int c = 0; c < 4; c++) {
            int h = h0 + r, w = w0 + c;
            float v = 0.0f;
            if (((unsigned)h < 32u) && ((unsigned)w < 32u))
                v = fmaxf(xs[h*32 + w], 0.0f);
            d[r][c] = v;
        }
    }
    float tr[4][4];
#pragma unroll
    for (int c = 0; c < 4; c++) {
        tr[0][c] = d[0][c] - d[2][c];
        tr[1][c] = d[1][c] + d[2][c];
        tr[2][c] = d[2][c] - d[1][c];
        tr[3][c] = d[1][c] - d[3][c];
    }
    float* o = g_T + ((((long)s*34 + (g1+1))*34 + (g2+1))*256 + tt)*16;
#pragma unroll
    for (int u = 0; u < 4; u++) {
        float V0 = tr[u][0] - tr[u][2];
        float V1 = tr[u][1] + tr[u][2];
        float V2 = tr[u][2] - tr[u][1];
        float V3 = tr[u][1] - tr[u][3];
        *(float4*)(o + u*4) = make_float4(V0, V1, V2, V3);
    }
}

// ---------------------------------------------------------------------------
// Kernel 2: transform-domain accumulate + inverse + sigmoid/mask/sum.
// CTA: (h1,w1) 4x4 region x 4x4 tile-block (8x8 h2w2) = 1024 outputs.
// 128 threads = tile-local tl(16) x uvp(8). 8 phases of (h1, w1-half).
// Tap-outer loop: 8 unconditional T-LDG.64 per tap (MLP 8), then per-s
// weights via immediate-offset LDS.128 and 16 fma2.
// SMEM: Wsm 1296 ull (10368 B) + M [2][16][136] fl (17408 B) = 27776 B.
// ---------------------------------------------------------------------------
#define SMEM_BYTES 27776
#define TS_S   4734976L   // 34*34*4096 floats
#define TS_G1  139264L    // 34*4096
#define TS_G2  4096L      // 256*16

__global__ __launch_bounds__(128, 6)
void conv_kernel(const float* __restrict__ x, float* __restrict__ out) {
    extern __shared__ float sm[];
    ull* Wsm = (ull*)sm;
    float* M = sm + 2592;

    const int tid = threadIdx.x;
    const int bid = blockIdx.x;
    const int B2  = bid & 3;
    const int B1  = (bid >> 2) & 3;
    const int bw1 = (bid >> 4) & 7;
    const int bh1 = bid >> 7;

    for (int i = tid; i < 1296; i += 128) Wsm[i] = g_wp2[i];

    const int uvp = tid & 7;
    const int tl  = tid >> 3;
    const int ta  = tl >> 2, tb = tl & 3;
    const long toff = (((B1*4 + ta)*16 + (B2*4 + tb))*16) + 2*uvp;
    const ulonglong2* Wq = (const ulonglong2*)Wsm;
    __syncthreads();

#pragma unroll 1
    for (int qb = 0; qb < 8; qb++) {
        const int h1  = qb >> 1;
        const int w1h = qb & 1;
        const int H1  = bh1*4 + h1;
        const int g2p0 = bw1*4 + w1h*2;      // padded g2 base

        // Per-s_in T base pointers (padded layout: no bounds checks anywhere)
        const float* Tb0 = g_T + ((0*34 + H1)*34 + g2p0)*TS_G2 + toff;
        const float* Tb1 = Tb0 + TS_S;
        const float* Tb2 = Tb1 + TS_S;
        const float* Tb3 = Tb2 + TS_S;

        ull acc[2][4][2];
#pragma unroll
        for (int wl = 0; wl < 2; wl++)
#pragma unroll
            for (int so = 0; so < 4; so++) { acc[wl][so][0] = 0ull; acc[wl][so][1] = 0ull; }

#pragma unroll
        for (int dh1 = 0; dh1 < 3; dh1++) {
#pragma unroll
            for (int dw1 = 0; dw1 < 3; dw1++) {
                // ---- 8 independent T loads (immediate offsets) ----
                ull tv[4][2];
#pragma unroll
                for (int wl = 0; wl < 2; wl++) {
                    const long o = dh1*TS_G1 + (dw1+wl)*TS_G2;
                    tv[0][wl] = *(const ull*)(Tb0 + o);
                    tv[1][wl] = *(const ull*)(Tb1 + o);
                    tv[2][wl] = *(const ull*)(Tb2 + o);
                    tv[3][wl] = *(const ull*)(Tb3 + o);
                }
                const int tap8 = (dh1*3 + dw1) * 8;
#pragma unroll
                for (int s = 0; s < 4; s++) {
                    const int s1i = s >> 1, s2i = s & 1;
                    // ds(s,so)*72 folds to a compile-time constant per (s,so)
                    ulonglong2 w0 = Wq[uvp + ((s1i+1)*3 + s2i+1)*72 + tap8];
                    ulonglong2 w1 = Wq[uvp + ((s1i+1)*3 + s2i  )*72 + tap8];
                    ulonglong2 w2 = Wq[uvp + (( s1i )*3 + s2i+1)*72 + tap8];
                    ulonglong2 w3 = Wq[uvp + (( s1i )*3 + s2i  )*72 + tap8];
#pragma unroll
                    for (int wl = 0; wl < 2; wl++) {
                        ull tvv = tv[s][wl];
                        acc[wl][0][0] = fma2(tvv, w0.x, acc[wl][0][0]);
                        acc[wl][0][1] = fma2(tvv, w0.y, acc[wl][0][1]);
                        acc[wl][1][0] = fma2(tvv, w1.x, acc[wl][1][0]);
                        acc[wl][1][1] = fma2(tvv, w1.y, acc[wl][1][1]);
                        acc[wl][2][0] = fma2(tvv, w2.x, acc[wl][2][0]);
                        acc[wl][2][1] = fma2(tvv, w2.y, acc[wl][2][1]);
                        acc[wl][3][0] = fma2(tvv, w3.x, acc[wl][3][0]);
                        acc[wl][3][1] = fma2(tvv, w3.y, acc[wl][3][1]);
                    }
                }
            }
        }

        __syncthreads();   // prior epilogue done; safe to overwrite M
#pragma unroll
        for (int wl = 0; wl < 2; wl++)
#pragma unroll
            for (int so = 0; so < 4; so++)
#pragma unroll
                for (int br = 0; br < 2; br++)
                    *(ull*)(M + (wl*16 + tl)*136 + (so*2 + br)*16 + 2*uvp)
                        = acc[wl][so][br];
        __syncthreads();

        // ---- inverse + sigmoid + mask + so-reduction ----
        {
            const int so = tid & 3;
            const int t  = (tid >> 2) & 15;
            const int wl = tid >> 6;
            const int w1 = w1h*2 + wl;
            const int W1 = bw1*4 + w1;
            const int ti = B1*4 + (t >> 2);
            const int tj = B2*4 + (t & 3);
            const float* mc = M + (wl*16 + t)*136 + so*32;

            float p[4] = {0.f, 0.f, 0.f, 0.f};
#pragma unroll
            for (int br = 0; br < 2; br++) {
                float m[16];
#pragma unroll
                for (int u = 0; u < 16; u += 4) {
                    float4 mv = *(const float4*)(mc + br*16 + u);
                    m[u] = mv.x; m[u+1] = mv.y; m[u+2] = mv.z; m[u+3] = mv.w;
                }
                float p0[4], p1[4];
#pragma unroll
                for (int c = 0; c < 4; c++) {
                    p0[c] = m[c] + m[4+c] + m[8+c];
                    p1[c] = m[4+c] - m[8+c] - m[12+c];
                }
                p[0] += sigm(p0[0] + p0[1] + p0[2]);
                p[1] += sigm(p0[1] - p0[2] - p0[3]);
                p[2] += sigm(p1[0] + p1[1] + p1[2]);
                p[3] += sigm(p1[1] - p1[2] - p1[3]);
            }
            const float* xs = x + so*1048576 + (H1*32 + W1)*1024 + (2*ti)*32 + 2*tj;
            float2 x0 = *(const float2*)xs;
            float2 x1 = *(const float2*)(xs + 32);
            p[0] = (x0.x != 0.0f) ? p[0] : 0.0f;
            p[1] = (x0.y != 0.0f) ? p[1] : 0.0f;
            p[2] = (x1.x != 0.0f) ? p[2] : 0.0f;
            p[3] = (x1.y != 0.0f) ? p[3] : 0.0f;
#pragma unroll
            for (int k = 0; k < 4; k++) {
                p[k] += __shfl_xor_sync(0xFFFFFFFFu, p[k], 1);
                p[k] += __shfl_xor_sync(0xFFFFFFFFu, p[k], 2);
            }
            if (so == 0) {
                float* op = out + (H1*32 + W1)*1024 + (2*ti)*32 + 2*tj;
                *(float2*)op        = make_float2(p[0], p[1]);
                *(float2*)(op + 32) = make_float2(p[2], p[3]);
            }
        }
    }
}

extern "C" void kernel_launch(void* const* d_in, const int* in_sizes, int n_in,
                              void* d_out, int out_size) {
    const float* x    = (const float*)d_in[0];   // (1,2,2,32,32,32,32)
    const float* kern = (const float*)d_in[1];   // (729,)
    float* out = (float*)d_out;                  // (1,32,32,32,32)

    xform_kernel<<<4097, 256>>>(x, kern);
    conv_kernel<<<1024, 128, SMEM_BYTES>>>(x, out);
}